// round 3
// baseline (speedup 1.0000x reference)
#include <cuda_runtime.h>
#include <cstdint>

// Problem constants (fixed by setup_inputs)
#define B_   4
#define S_   4096
#define D_   1024
#define H_   16
#define KD   64
#define NW   8
#define SW   512            // S_/NW
#define MROWS (B_*S_)       // 16384

// ---------------- device scratch (no allocations allowed) ----------------
__device__ float g_q[(size_t)MROWS * D_];    // also reused as y = x + attn_out
__device__ float g_k[(size_t)MROWS * D_];
__device__ float g_v[(size_t)MROWS * D_];
__device__ float g_ctx[(size_t)MROWS * D_];

// ==========================================================================
// Tensor-core FP32 GEMM via 3xTF32 mma.sync (m16n8k8), double-buffered smem.
// C[M,1024] = A[M,1024] * W[1024,1024] + bias (+ residual)
// Block: 128x128 tile, BK=16, 256 threads = 8 warps (2x4), warp tile 64x32.
// Precision: a = aHi + aLo (tf32 split); product = aHi*bHi + aHi*bLo + aLo*bHi
// -> ~fp32 accuracy, fp32 accumulate.
// ==========================================================================
#define BM 128
#define BN 128
#define BK 16
#define AS_STRIDE 20    // 16 + 4 pad: (m*20 + k) banks conflict-free for frags
#define BS_STRIDE 136   // 128 + 8 pad: stride ≡ 8 (mod 32) -> conflict-free

__device__ __forceinline__ void split_tf32(float x, uint32_t& hi, uint32_t& lo)
{
    asm("cvt.rna.tf32.f32 %0, %1;" : "=r"(hi) : "f"(x));
    float rem = x - __uint_as_float(hi);
    asm("cvt.rna.tf32.f32 %0, %1;" : "=r"(lo) : "f"(rem));
}

__device__ __forceinline__ void mma_tf32(float c[4], uint32_t a0, uint32_t a1,
                                         uint32_t a2, uint32_t a3,
                                         uint32_t b0, uint32_t b1)
{
    asm volatile(
        "mma.sync.aligned.m16n8k8.row.col.f32.tf32.tf32.f32 "
        "{%0,%1,%2,%3}, {%4,%5,%6,%7}, {%8,%9}, {%0,%1,%2,%3};"
        : "+f"(c[0]), "+f"(c[1]), "+f"(c[2]), "+f"(c[3])
        : "r"(a0), "r"(a1), "r"(a2), "r"(a3), "r"(b0), "r"(b1));
}

__device__ __forceinline__ void gemm_tile_tc(
    const float* __restrict__ A, const float* __restrict__ Wm,
    const float* __restrict__ bias, const float* __restrict__ res,
    float* __restrict__ C)
{
    const int t    = threadIdx.x;
    const int lane = t & 31;
    const int warp = t >> 5;
    const int wm   = (warp & 1) * 64;    // warp row offset in tile
    const int wn   = (warp >> 1) * 32;   // warp col offset in tile
    const int lr   = lane >> 2;          // 0..7
    const int lc   = lane & 3;           // 0..3
    const int rowBase = blockIdx.y * BM;
    const int colBase = blockIdx.x * BN;
    const int N = 1024, Kd = 1024;

    __shared__ float As[2][BM][AS_STRIDE];  // A[m][k], double buffered
    __shared__ float Bs[2][BK][BS_STRIDE];  // W[k][n], double buffered

    // Per-thread load coordinates (constant across iterations)
    const int arow0 = t >> 2;              // A: rows t/4, t/4+64
    const int acg   = (t & 3) << 2;
    const int brow0 = t >> 5;              // B: k-rows t/32, t/32+8
    const int bcg   = (t & 31) << 2;

    float acc[4][4][4];                  // [mi][ni][reg]
#pragma unroll
    for (int mi = 0; mi < 4; mi++)
#pragma unroll
        for (int ni = 0; ni < 4; ni++)
#pragma unroll
            for (int r = 0; r < 4; r++) acc[mi][ni][r] = 0.f;

    // ---- preload tile 0 into buffer 0 ----
    {
        *(float4*)(&As[0][arow0     ][acg]) =
            *(const float4*)(A + (size_t)(rowBase + arow0     ) * Kd + acg);
        *(float4*)(&As[0][arow0 + 64][acg]) =
            *(const float4*)(A + (size_t)(rowBase + arow0 + 64) * Kd + acg);
        *(float4*)(&Bs[0][brow0    ][bcg]) =
            *(const float4*)(Wm + (size_t)(brow0    ) * N + colBase + bcg);
        *(float4*)(&Bs[0][brow0 + 8][bcg]) =
            *(const float4*)(Wm + (size_t)(brow0 + 8) * N + colBase + bcg);
    }
    __syncthreads();

    int buf = 0;
    for (int k0 = 0; k0 < Kd; k0 += BK, buf ^= 1) {
        // ---- prefetch next tile into registers (issued before MMA work) ----
        float4 pa0, pa1, pb0, pb1;
        const bool has_next = (k0 + BK) < Kd;
        if (has_next) {
            const int kn = k0 + BK;
            pa0 = *(const float4*)(A + (size_t)(rowBase + arow0     ) * Kd + kn + acg);
            pa1 = *(const float4*)(A + (size_t)(rowBase + arow0 + 64) * Kd + kn + acg);
            pb0 = *(const float4*)(Wm + (size_t)(kn + brow0    ) * N + colBase + bcg);
            pb1 = *(const float4*)(Wm + (size_t)(kn + brow0 + 8) * N + colBase + bcg);
        }

        // ---- MMA on current buffer ----
#pragma unroll
        for (int kc = 0; kc < BK; kc += 8) {
            uint32_t aHi[4][4], aLo[4][4];
#pragma unroll
            for (int mi = 0; mi < 4; mi++) {
                const int m0 = wm + mi * 16 + lr;
                split_tf32(As[buf][m0    ][kc + lc    ], aHi[mi][0], aLo[mi][0]);
                split_tf32(As[buf][m0 + 8][kc + lc    ], aHi[mi][1], aLo[mi][1]);
                split_tf32(As[buf][m0    ][kc + lc + 4], aHi[mi][2], aLo[mi][2]);
                split_tf32(As[buf][m0 + 8][kc + lc + 4], aHi[mi][3], aLo[mi][3]);
            }
#pragma unroll
            for (int ni = 0; ni < 4; ni++) {
                const int n0 = wn + ni * 8 + lr;
                uint32_t bHi0, bLo0, bHi1, bLo1;
                split_tf32(Bs[buf][kc + lc    ][n0], bHi0, bLo0);
                split_tf32(Bs[buf][kc + lc + 4][n0], bHi1, bLo1);
#pragma unroll
                for (int mi = 0; mi < 4; mi++) {
                    mma_tf32(acc[mi][ni], aHi[mi][0], aHi[mi][1], aHi[mi][2], aHi[mi][3], bHi0, bHi1);
                    mma_tf32(acc[mi][ni], aLo[mi][0], aLo[mi][1], aLo[mi][2], aLo[mi][3], bHi0, bHi1);
                    mma_tf32(acc[mi][ni], aHi[mi][0], aHi[mi][1], aHi[mi][2], aHi[mi][3], bLo0, bLo1);
                }
            }
        }

        // ---- store prefetched tile into the other buffer ----
        if (has_next) {
            const int nb = buf ^ 1;
            *(float4*)(&As[nb][arow0     ][acg]) = pa0;
            *(float4*)(&As[nb][arow0 + 64][acg]) = pa1;
            *(float4*)(&Bs[nb][brow0    ][bcg]) = pb0;
            *(float4*)(&Bs[nb][brow0 + 8][bcg]) = pb1;
        }
        __syncthreads();
    }

    // Epilogue: bias (+ residual); c frag: rows lr / lr+8, cols lc*2, lc*2+1
#pragma unroll
    for (int mi = 0; mi < 4; mi++) {
        const int row0 = rowBase + wm + mi * 16 + lr;
        const int row1 = row0 + 8;
#pragma unroll
        for (int ni = 0; ni < 4; ni++) {
            const int col = colBase + wn + ni * 8 + lc * 2;
            const float b0 = bias[col], b1 = bias[col + 1];
            float2 v0 = make_float2(acc[mi][ni][0] + b0, acc[mi][ni][1] + b1);
            float2 v1 = make_float2(acc[mi][ni][2] + b0, acc[mi][ni][3] + b1);
            if (res) {
                const float2 r0 = *(const float2*)(res + (size_t)row0 * N + col);
                const float2 r1 = *(const float2*)(res + (size_t)row1 * N + col);
                v0.x += r0.x; v0.y += r0.y;
                v1.x += r1.x; v1.y += r1.y;
            }
            *(float2*)(C + (size_t)row0 * N + col) = v0;
            *(float2*)(C + (size_t)row1 * N + col) = v1;
        }
    }
}

__global__ __launch_bounds__(256) void qkv_kernel(
    const float* __restrict__ x,
    const float* __restrict__ Wq, const float* __restrict__ Wk, const float* __restrict__ Wv,
    const float* __restrict__ bq, const float* __restrict__ bk, const float* __restrict__ bv)
{
    const int z = blockIdx.z;
    const float* W = (z == 0) ? Wq : (z == 1) ? Wk : Wv;
    const float* b = (z == 0) ? bq : (z == 1) ? bk : bv;
    float*       C = (z == 0) ? g_q : (z == 1) ? g_k : g_v;
    gemm_tile_tc(x, W, b, nullptr, C);
}

__global__ __launch_bounds__(256) void oproj_kernel(
    const float* __restrict__ Wo, const float* __restrict__ bo,
    const float* __restrict__ x)
{
    gemm_tile_tc(g_ctx, Wo, bo, x, g_q);   // y = ctx @ Wo + bo + x  -> g_q
}

// ==========================================================================
// Windowed flash attention (FFMA; ~34 GF total, ~100 us predicted).
// Block: 64 q-rows of one (b, w, h). 256 threads. KV chunks of 32.
// ==========================================================================
#define TQ 64
#define TC 32

__global__ __launch_bounds__(256) void attn_kernel()
{
    __shared__ float Qs[TQ][KD];          // pre-scaled by 1/8
    __shared__ float Ks[TC][KD + 4];
    __shared__ float Vs[TC][KD];
    __shared__ float Ssm[TQ][TC + 1];
    __shared__ float Msm[TQ], Lsm[TQ], Asm[TQ];

    const int t   = threadIdx.x;
    const int qt  = blockIdx.x;           // 0..7
    const int bwh = blockIdx.y;           // 0..511
    const int h = bwh & 15;
    const int w = (bwh >> 4) & 7;
    const int b = bwh >> 7;

    const size_t rowStride = (size_t)H_ * KD;   // 1024
    const float* qptr = g_q + ((size_t)(b * S_ + w * SW + qt * TQ) * H_ + h) * KD;
    const float* kptr = g_k + ((size_t)(b * S_ + w * SW) * H_ + h) * KD;
    const float* vptr = g_v + ((size_t)(b * S_ + w * SW) * H_ + h) * KD;

#pragma unroll
    for (int l = 0; l < 4; l++) {
        int idx = t + l * 256;
        int r   = idx >> 4;
        int dg  = (idx & 15) << 2;
        float4 a = *(const float4*)(qptr + (size_t)r * rowStride + dg);
        *(float4*)(&Qs[r][dg]) =
            make_float4(a.x * 0.125f, a.y * 0.125f, a.z * 0.125f, a.w * 0.125f);
    }
    if (t < TQ) { Msm[t] = -1e30f; Lsm[t] = 0.f; }

    const int r  = t >> 2;                // 0..63 (owned q row)
    const int tq = t & 3;

    float acc[4][4];
#pragma unroll
    for (int jj = 0; jj < 4; jj++)
#pragma unroll
        for (int e = 0; e < 4; e++) acc[jj][e] = 0.f;

    for (int ch = 0; ch < SW / TC; ch++) {
#pragma unroll
        for (int l = 0; l < 2; l++) {
            int idx = t + l * 256;
            int c   = idx >> 4;
            int dg  = (idx & 15) << 2;
            const size_t goff = (size_t)(ch * TC + c) * rowStride + dg;
            *(float4*)(&Ks[c][dg]) = *(const float4*)(kptr + goff);
            *(float4*)(&Vs[c][dg]) = *(const float4*)(vptr + goff);
        }
        __syncthreads();

        float s[8];
#pragma unroll
        for (int i = 0; i < 8; i++) s[i] = 0.f;
#pragma unroll
        for (int d4 = 0; d4 < KD / 4; d4++) {
            const float4 q4 = *(const float4*)(&Qs[r][d4 * 4]);
#pragma unroll
            for (int i = 0; i < 8; i++) {
                const float4 k4 = *(const float4*)(&Ks[tq + 4 * i][d4 * 4]);
                s[i] = fmaf(q4.x, k4.x, s[i]);
                s[i] = fmaf(q4.y, k4.y, s[i]);
                s[i] = fmaf(q4.z, k4.z, s[i]);
                s[i] = fmaf(q4.w, k4.w, s[i]);
            }
        }
#pragma unroll
        for (int i = 0; i < 8; i++) Ssm[r][tq + 4 * i] = s[i];
        __syncthreads();

        if (t < TQ) {
            float mo = Msm[t];
            float mx = mo;
#pragma unroll
            for (int c = 0; c < TC; c++) mx = fmaxf(mx, Ssm[t][c]);
            float alpha = __expf(mo - mx);
            float sum = 0.f;
#pragma unroll
            for (int c = 0; c < TC; c++) {
                float p = __expf(Ssm[t][c] - mx);
                Ssm[t][c] = p;
                sum += p;
            }
            Msm[t] = mx;
            Lsm[t] = Lsm[t] * alpha + sum;
            Asm[t] = alpha;
        }
        __syncthreads();

        const float alpha = Asm[r];
#pragma unroll
        for (int jj = 0; jj < 4; jj++)
#pragma unroll
            for (int e = 0; e < 4; e++) acc[jj][e] *= alpha;

#pragma unroll
        for (int c = 0; c < TC; c++) {
            const float p = Ssm[r][c];
#pragma unroll
            for (int jj = 0; jj < 4; jj++) {
                const float4 v4 = *(const float4*)(&Vs[c][tq * 4 + 16 * jj]);
                acc[jj][0] = fmaf(p, v4.x, acc[jj][0]);
                acc[jj][1] = fmaf(p, v4.y, acc[jj][1]);
                acc[jj][2] = fmaf(p, v4.z, acc[jj][2]);
                acc[jj][3] = fmaf(p, v4.w, acc[jj][3]);
            }
        }
        __syncthreads();
    }

    const float invl = 1.f / Lsm[r];
    const int srow = w * SW + qt * TQ + r;
    float* cptr = g_ctx + (size_t)(b * S_ + srow) * D_ + h * KD;
#pragma unroll
    for (int jj = 0; jj < 4; jj++) {
        *(float4*)(cptr + tq * 4 + 16 * jj) =
            make_float4(acc[jj][0] * invl, acc[jj][1] * invl,
                        acc[jj][2] * invl, acc[jj][3] * invl);
    }
}

// ==========================================================================
// LayerNorm (eps = 1e-3) over last dim 1024. One block (256 thr) per row.
// ==========================================================================
__global__ __launch_bounds__(256) void ln_kernel(
    const float* __restrict__ gamma, const float* __restrict__ beta,
    float* __restrict__ out)
{
    const int row = blockIdx.x;
    const int t = threadIdx.x;
    const float4 v = ((const float4*)(g_q + (size_t)row * D_))[t];

    float s  = v.x + v.y + v.z + v.w;
    float sq = v.x * v.x + v.y * v.y + v.z * v.z + v.w * v.w;

    __shared__ float red[2][8];
#pragma unroll
    for (int o = 16; o; o >>= 1) {
        s  += __shfl_xor_sync(0xffffffffu, s,  o);
        sq += __shfl_xor_sync(0xffffffffu, sq, o);
    }
    if ((t & 31) == 0) { red[0][t >> 5] = s; red[1][t >> 5] = sq; }
    __syncthreads();
    if (t < 32) {
        float a  = (t < 8) ? red[0][t] : 0.f;
        float b2 = (t < 8) ? red[1][t] : 0.f;
#pragma unroll
        for (int o = 4; o; o >>= 1) {
            a  += __shfl_xor_sync(0xffffffffu, a,  o);
            b2 += __shfl_xor_sync(0xffffffffu, b2, o);
        }
        if (t == 0) { red[0][0] = a; red[1][0] = b2; }
    }
    __syncthreads();

    const float mean = red[0][0] * (1.f / 1024.f);
    const float var  = red[1][0] * (1.f / 1024.f) - mean * mean;
    const float rstd = rsqrtf(var + 1e-3f);

    const float4 g4 = ((const float4*)gamma)[t];
    const float4 b4 = ((const float4*)beta)[t];
    float4 o4;
    o4.x = (v.x - mean) * rstd * g4.x + b4.x;
    o4.y = (v.y - mean) * rstd * g4.y + b4.y;
    o4.z = (v.z - mean) * rstd * g4.z + b4.z;
    o4.w = (v.w - mean) * rstd * g4.w + b4.w;
    ((float4*)out)[(size_t)row * (D_ / 4) + t] = o4;
}

// ==========================================================================
// kernel_launch
// Inputs: 0 x, 1 Wq, 2 bq, 3 Wk, 4 bk, 5 Wv, 6 bv, 7 Wo, 8 bo, 9 gamma,
//         10 beta, 11 num_window
// ==========================================================================
extern "C" void kernel_launch(void* const* d_in, const int* in_sizes, int n_in,
                              void* d_out, int out_size)
{
    const float* x     = (const float*)d_in[0];
    const float* Wq    = (const float*)d_in[1];
    const float* bq    = (const float*)d_in[2];
    const float* Wk    = (const float*)d_in[3];
    const float* bk    = (const float*)d_in[4];
    const float* Wv    = (const float*)d_in[5];
    const float* bv    = (const float*)d_in[6];
    const float* Wo    = (const float*)d_in[7];
    const float* bo    = (const float*)d_in[8];
    const float* gamma = (const float*)d_in[9];
    const float* beta  = (const float*)d_in[10];
    float* out = (float*)d_out;

    (void)in_sizes; (void)n_in; (void)out_size;

    // 1. QKV projections (tensor-core 3xTF32, double-buffered)
    dim3 gq(D_ / BN, MROWS / BM, 3);
    qkv_kernel<<<gq, 256>>>(x, Wq, Wk, Wv, bq, bk, bv);

    // 2. Windowed attention
    dim3 ga(SW / TQ, B_ * NW * H_);
    attn_kernel<<<ga, 256>>>();

    // 3. Output projection + residual -> g_q (as y)
    dim3 go(D_ / BN, MROWS / BM, 1);
    oproj_kernel<<<go, 256>>>(Wo, bo, x);

    // 4. LayerNorm -> out
    ln_kernel<<<MROWS, 256>>>(gamma, beta, out);
}

// round 7
// speedup vs baseline: 1.1900x; 1.1900x over previous
#include <cuda_runtime.h>
#include <cstdint>

// Problem constants (fixed by setup_inputs)
#define B_   4
#define S_   4096
#define D_   1024
#define H_   16
#define KD   64
#define NW   8
#define SW   512            // S_/NW
#define MROWS (B_*S_)       // 16384

// ---------------- device scratch (no allocations allowed) ----------------
__device__ float g_q[(size_t)MROWS * D_];    // also reused as y = x + attn_out
__device__ float g_k[(size_t)MROWS * D_];
__device__ float g_v[(size_t)MROWS * D_];
__device__ float g_ctx[(size_t)MROWS * D_];

// ==========================================================================
// Tensor-core GEMM via 2-term split-TF32 mma.sync (m16n8k8).
// C[M,1024] = A[M,1024] * W[1024,1024] + bias (+ residual)
//
// A is pre-split into (hi, lo) tf32 planes IN SMEM at tile-load time;
// B is single-rounded to tf32 at tile-load time. Inner loop is pure LDS+MMA.
// product = (aHi + aLo) * rna(b)  ->  rel err ~2^-12 per product, ~1e-4 out.
//
// Block: 128x128 tile, BK=8, 256 threads = 8 warps (2x4), warp tile 64x32.
// Double-buffered smem; per-iter register prefetch of the next tile.
// ==========================================================================
#define BM 128
#define BN 128
#define BK 8
#define AS_STRIDE 12    // (lr*12 + lc) mod 32 covers all banks -> conflict-free
#define BS_STRIDE 136   // 128+8: (lc*8 + lr) conflict-free for frag & STS

__device__ __forceinline__ uint32_t to_tf32(float x)
{
    uint32_t r;
    asm("cvt.rna.tf32.f32 %0, %1;" : "=r"(r) : "f"(x));
    return r;
}

__device__ __forceinline__ void split_tf32(float x, uint32_t& hi, uint32_t& lo)
{
    asm("cvt.rna.tf32.f32 %0, %1;" : "=r"(hi) : "f"(x));
    float rem = x - __uint_as_float(hi);
    asm("cvt.rna.tf32.f32 %0, %1;" : "=r"(lo) : "f"(rem));
}

__device__ __forceinline__ void mma_tf32(float c[4], uint32_t a0, uint32_t a1,
                                         uint32_t a2, uint32_t a3,
                                         uint32_t b0, uint32_t b1)
{
    asm volatile(
        "mma.sync.aligned.m16n8k8.row.col.f32.tf32.tf32.f32 "
        "{%0,%1,%2,%3}, {%4,%5,%6,%7}, {%8,%9}, {%0,%1,%2,%3};"
        : "+f"(c[0]), "+f"(c[1]), "+f"(c[2]), "+f"(c[3])
        : "r"(a0), "r"(a1), "r"(a2), "r"(a3), "r"(b0), "r"(b1));
}

__device__ __forceinline__ void gemm_tile_tc(
    const float* __restrict__ A, const float* __restrict__ Wm,
    const float* __restrict__ bias, const float* __restrict__ res,
    float* __restrict__ C)
{
    const int t    = threadIdx.x;
    const int lane = t & 31;
    const int warp = t >> 5;
    const int wm   = (warp & 1) * 64;    // warp row offset in tile
    const int wn   = (warp >> 1) * 32;   // warp col offset in tile
    const int lr   = lane >> 2;          // 0..7
    const int lc   = lane & 3;           // 0..3
    const int rowBase = blockIdx.y * BM;
    const int colBase = blockIdx.x * BN;
    const int N = 1024, Kd = 1024;

    // [buf][plane hi=0/lo=1][m][k]
    __shared__ uint32_t As[2][2][BM][AS_STRIDE];
    // [buf][k][n]
    __shared__ uint32_t Bs[2][BK][BS_STRIDE];

    // Per-thread load coordinates (constant across iterations)
    const int arow = t >> 1;              // 0..127
    const int acg  = (t & 1) << 2;        // 0 or 4
    const int brow = t >> 5;              // 0..7
    const int bcg  = (t & 31) << 2;       // 0..124

    const float* aSrc = A  + (size_t)(rowBase + arow) * Kd + acg;
    const float* bSrc = Wm + (size_t)brow * N + colBase + bcg;

    float acc[4][4][4];                  // [mi][ni][reg]
#pragma unroll
    for (int mi = 0; mi < 4; mi++)
#pragma unroll
        for (int ni = 0; ni < 4; ni++)
#pragma unroll
            for (int r = 0; r < 4; r++) acc[mi][ni][r] = 0.f;

    // ---- preload tile 0 into buffer 0 ----
    {
        float4 a4 = *(const float4*)(aSrc);
        float4 b4 = *(const float4*)(bSrc);
        uint32_t h0,l0,h1,l1,h2,l2,h3,l3;
        split_tf32(a4.x, h0, l0); split_tf32(a4.y, h1, l1);
        split_tf32(a4.z, h2, l2); split_tf32(a4.w, h3, l3);
        *(uint4*)(&As[0][0][arow][acg]) = make_uint4(h0, h1, h2, h3);
        *(uint4*)(&As[0][1][arow][acg]) = make_uint4(l0, l1, l2, l3);
        *(uint4*)(&Bs[0][brow][bcg]) =
            make_uint4(to_tf32(b4.x), to_tf32(b4.y), to_tf32(b4.z), to_tf32(b4.w));
    }
    __syncthreads();

    int buf = 0;
    for (int k0 = 0; k0 < Kd; k0 += BK, buf ^= 1) {
        // ---- prefetch next tile into registers ----
        float4 pa, pb;
        const bool has_next = (k0 + BK) < Kd;
        if (has_next) {
            pa = *(const float4*)(aSrc + (k0 + BK));
            pb = *(const float4*)(bSrc + (size_t)(k0 + BK) * N);
        }

        // ---- fragments from current buffer (pure LDS, no cvt) ----
        uint32_t aHi[4][4], aLo[4][4], bF[4][2];
#pragma unroll
        for (int mi = 0; mi < 4; mi++) {
            const int m0 = wm + mi * 16 + lr;
            aHi[mi][0] = As[buf][0][m0    ][lc    ];
            aHi[mi][1] = As[buf][0][m0 + 8][lc    ];
            aHi[mi][2] = As[buf][0][m0    ][lc + 4];
            aHi[mi][3] = As[buf][0][m0 + 8][lc + 4];
            aLo[mi][0] = As[buf][1][m0    ][lc    ];
            aLo[mi][1] = As[buf][1][m0 + 8][lc    ];
            aLo[mi][2] = As[buf][1][m0    ][lc + 4];
            aLo[mi][3] = As[buf][1][m0 + 8][lc + 4];
        }
#pragma unroll
        for (int ni = 0; ni < 4; ni++) {
            const int n0 = wn + ni * 8 + lr;
            bF[ni][0] = Bs[buf][lc    ][n0];
            bF[ni][1] = Bs[buf][lc + 4][n0];
        }

        // ---- 32 MMAs: hi*b + lo*b ----
#pragma unroll
        for (int ni = 0; ni < 4; ni++)
#pragma unroll
            for (int mi = 0; mi < 4; mi++) {
                mma_tf32(acc[mi][ni], aHi[mi][0], aHi[mi][1], aHi[mi][2], aHi[mi][3],
                         bF[ni][0], bF[ni][1]);
                mma_tf32(acc[mi][ni], aLo[mi][0], aLo[mi][1], aLo[mi][2], aLo[mi][3],
                         bF[ni][0], bF[ni][1]);
            }

        // ---- split/round prefetched tile into other buffer ----
        if (has_next) {
            const int nb = buf ^ 1;
            uint32_t h0,l0,h1,l1,h2,l2,h3,l3;
            split_tf32(pa.x, h0, l0); split_tf32(pa.y, h1, l1);
            split_tf32(pa.z, h2, l2); split_tf32(pa.w, h3, l3);
            *(uint4*)(&As[nb][0][arow][acg]) = make_uint4(h0, h1, h2, h3);
            *(uint4*)(&As[nb][1][arow][acg]) = make_uint4(l0, l1, l2, l3);
            *(uint4*)(&Bs[nb][brow][bcg]) =
                make_uint4(to_tf32(pb.x), to_tf32(pb.y), to_tf32(pb.z), to_tf32(pb.w));
        }
        __syncthreads();
    }

    // Epilogue: bias (+ residual); c frag: rows lr / lr+8, cols lc*2, lc*2+1
#pragma unroll
    for (int mi = 0; mi < 4; mi++) {
        const int row0 = rowBase + wm + mi * 16 + lr;
        const int row1 = row0 + 8;
#pragma unroll
        for (int ni = 0; ni < 4; ni++) {
            const int col = colBase + wn + ni * 8 + lc * 2;
            const float b0 = bias[col], b1 = bias[col + 1];
            float2 v0 = make_float2(acc[mi][ni][0] + b0, acc[mi][ni][1] + b1);
            float2 v1 = make_float2(acc[mi][ni][2] + b0, acc[mi][ni][3] + b1);
            if (res) {
                const float2 r0 = *(const float2*)(res + (size_t)row0 * N + col);
                const float2 r1 = *(const float2*)(res + (size_t)row1 * N + col);
                v0.x += r0.x; v0.y += r0.y;
                v1.x += r1.x; v1.y += r1.y;
            }
            *(float2*)(C + (size_t)row0 * N + col) = v0;
            *(float2*)(C + (size_t)row1 * N + col) = v1;
        }
    }
}

__global__ __launch_bounds__(256) void qkv_kernel(
    const float* __restrict__ x,
    const float* __restrict__ Wq, const float* __restrict__ Wk, const float* __restrict__ Wv,
    const float* __restrict__ bq, const float* __restrict__ bk, const float* __restrict__ bv)
{
    const int z = blockIdx.z;
    const float* W = (z == 0) ? Wq : (z == 1) ? Wk : Wv;
    const float* b = (z == 0) ? bq : (z == 1) ? bk : bv;
    float*       C = (z == 0) ? g_q : (z == 1) ? g_k : g_v;
    gemm_tile_tc(x, W, b, nullptr, C);
}

__global__ __launch_bounds__(256) void oproj_kernel(
    const float* __restrict__ Wo, const float* __restrict__ bo,
    const float* __restrict__ x)
{
    gemm_tile_tc(g_ctx, Wo, bo, x, g_q);   // y = ctx @ Wo + bo + x  -> g_q
}

// ==========================================================================
// Windowed flash attention (FFMA).
// Block: 64 q-rows of one (b, w, h). 256 threads. KV chunks of 32.
// ==========================================================================
#define TQ 64
#define TC 32

__global__ __launch_bounds__(256) void attn_kernel()
{
    __shared__ float Qs[TQ][KD];          // pre-scaled by 1/8
    __shared__ float Ks[TC][KD + 4];
    __shared__ float Vs[TC][KD];
    __shared__ float Ssm[TQ][TC + 1];
    __shared__ float Msm[TQ], Lsm[TQ], Asm[TQ];

    const int t   = threadIdx.x;
    const int qt  = blockIdx.x;           // 0..7
    const int bwh = blockIdx.y;           // 0..511
    const int h = bwh & 15;
    const int w = (bwh >> 4) & 7;
    const int b = bwh >> 7;

    const size_t rowStride = (size_t)H_ * KD;   // 1024
    const float* qptr = g_q + ((size_t)(b * S_ + w * SW + qt * TQ) * H_ + h) * KD;
    const float* kptr = g_k + ((size_t)(b * S_ + w * SW) * H_ + h) * KD;
    const float* vptr = g_v + ((size_t)(b * S_ + w * SW) * H_ + h) * KD;

#pragma unroll
    for (int l = 0; l < 4; l++) {
        int idx = t + l * 256;
        int r   = idx >> 4;
        int dg  = (idx & 15) << 2;
        float4 a = *(const float4*)(qptr + (size_t)r * rowStride + dg);
        *(float4*)(&Qs[r][dg]) =
            make_float4(a.x * 0.125f, a.y * 0.125f, a.z * 0.125f, a.w * 0.125f);
    }
    if (t < TQ) { Msm[t] = -1e30f; Lsm[t] = 0.f; }

    const int r  = t >> 2;                // 0..63 (owned q row)
    const int tq = t & 3;

    float acc[4][4];
#pragma unroll
    for (int jj = 0; jj < 4; jj++)
#pragma unroll
        for (int e = 0; e < 4; e++) acc[jj][e] = 0.f;

    for (int ch = 0; ch < SW / TC; ch++) {
#pragma unroll
        for (int l = 0; l < 2; l++) {
            int idx = t + l * 256;
            int c   = idx >> 4;
            int dg  = (idx & 15) << 2;
            const size_t goff = (size_t)(ch * TC + c) * rowStride + dg;
            *(float4*)(&Ks[c][dg]) = *(const float4*)(kptr + goff);
            *(float4*)(&Vs[c][dg]) = *(const float4*)(vptr + goff);
        }
        __syncthreads();

        float s[8];
#pragma unroll
        for (int i = 0; i < 8; i++) s[i] = 0.f;
#pragma unroll
        for (int d4 = 0; d4 < KD / 4; d4++) {
            const float4 q4 = *(const float4*)(&Qs[r][d4 * 4]);
#pragma unroll
            for (int i = 0; i < 8; i++) {
                const float4 k4 = *(const float4*)(&Ks[tq + 4 * i][d4 * 4]);
                s[i] = fmaf(q4.x, k4.x, s[i]);
                s[i] = fmaf(q4.y, k4.y, s[i]);
                s[i] = fmaf(q4.z, k4.z, s[i]);
                s[i] = fmaf(q4.w, k4.w, s[i]);
            }
        }
#pragma unroll
        for (int i = 0; i < 8; i++) Ssm[r][tq + 4 * i] = s[i];
        __syncthreads();

        if (t < TQ) {
            float mo = Msm[t];
            float mx = mo;
#pragma unroll
            for (int c = 0; c < TC; c++) mx = fmaxf(mx, Ssm[t][c]);
            float alpha = __expf(mo - mx);
            float sum = 0.f;
#pragma unroll
            for (int c = 0; c < TC; c++) {
                float p = __expf(Ssm[t][c] - mx);
                Ssm[t][c] = p;
                sum += p;
            }
            Msm[t] = mx;
            Lsm[t] = Lsm[t] * alpha + sum;
            Asm[t] = alpha;
        }
        __syncthreads();

        const float alpha = Asm[r];
#pragma unroll
        for (int jj = 0; jj < 4; jj++)
#pragma unroll
            for (int e = 0; e < 4; e++) acc[jj][e] *= alpha;

#pragma unroll
        for (int c = 0; c < TC; c++) {
            const float p = Ssm[r][c];
#pragma unroll
            for (int jj = 0; jj < 4; jj++) {
                const float4 v4 = *(const float4*)(&Vs[c][tq * 4 + 16 * jj]);
                acc[jj][0] = fmaf(p, v4.x, acc[jj][0]);
                acc[jj][1] = fmaf(p, v4.y, acc[jj][1]);
                acc[jj][2] = fmaf(p, v4.z, acc[jj][2]);
                acc[jj][3] = fmaf(p, v4.w, acc[jj][3]);
            }
        }
        __syncthreads();
    }

    const float invl = 1.f / Lsm[r];
    const int srow = w * SW + qt * TQ + r;
    float* cptr = g_ctx + (size_t)(b * S_ + srow) * D_ + h * KD;
#pragma unroll
    for (int jj = 0; jj < 4; jj++) {
        *(float4*)(cptr + tq * 4 + 16 * jj) =
            make_float4(acc[jj][0] * invl, acc[jj][1] * invl,
                        acc[jj][2] * invl, acc[jj][3] * invl);
    }
}

// ==========================================================================
// LayerNorm (eps = 1e-3) over last dim 1024. One block (256 thr) per row.
// ==========================================================================
__global__ __launch_bounds__(256) void ln_kernel(
    const float* __restrict__ gamma, const float* __restrict__ beta,
    float* __restrict__ out)
{
    const int row = blockIdx.x;
    const int t = threadIdx.x;
    const float4 v = ((const float4*)(g_q + (size_t)row * D_))[t];

    float s  = v.x + v.y + v.z + v.w;
    float sq = v.x * v.x + v.y * v.y + v.z * v.z + v.w * v.w;

    __shared__ float red[2][8];
#pragma unroll
    for (int o = 16; o; o >>= 1) {
        s  += __shfl_xor_sync(0xffffffffu, s,  o);
        sq += __shfl_xor_sync(0xffffffffu, sq, o);
    }
    if ((t & 31) == 0) { red[0][t >> 5] = s; red[1][t >> 5] = sq; }
    __syncthreads();
    if (t < 32) {
        float a  = (t < 8) ? red[0][t] : 0.f;
        float b2 = (t < 8) ? red[1][t] : 0.f;
#pragma unroll
        for (int o = 4; o; o >>= 1) {
            a  += __shfl_xor_sync(0xffffffffu, a,  o);
            b2 += __shfl_xor_sync(0xffffffffu, b2, o);
        }
        if (t == 0) { red[0][0] = a; red[1][0] = b2; }
    }
    __syncthreads();

    const float mean = red[0][0] * (1.f / 1024.f);
    const float var  = red[1][0] * (1.f / 1024.f) - mean * mean;
    const float rstd = rsqrtf(var + 1e-3f);

    const float4 g4 = ((const float4*)gamma)[t];
    const float4 b4 = ((const float4*)beta)[t];
    float4 o4;
    o4.x = (v.x - mean) * rstd * g4.x + b4.x;
    o4.y = (v.y - mean) * rstd * g4.y + b4.y;
    o4.z = (v.z - mean) * rstd * g4.z + b4.z;
    o4.w = (v.w - mean) * rstd * g4.w + b4.w;
    ((float4*)out)[(size_t)row * (D_ / 4) + t] = o4;
}

// ==========================================================================
// kernel_launch
// Inputs: 0 x, 1 Wq, 2 bq, 3 Wk, 4 bk, 5 Wv, 6 bv, 7 Wo, 8 bo, 9 gamma,
//         10 beta, 11 num_window
// ==========================================================================
extern "C" void kernel_launch(void* const* d_in, const int* in_sizes, int n_in,
                              void* d_out, int out_size)
{
    const float* x     = (const float*)d_in[0];
    const float* Wq    = (const float*)d_in[1];
    const float* bq    = (const float*)d_in[2];
    const float* Wk    = (const float*)d_in[3];
    const float* bk    = (const float*)d_in[4];
    const float* Wv    = (const float*)d_in[5];
    const float* bv    = (const float*)d_in[6];
    const float* Wo    = (const float*)d_in[7];
    const float* bo    = (const float*)d_in[8];
    const float* gamma = (const float*)d_in[9];
    const float* beta  = (const float*)d_in[10];
    float* out = (float*)d_out;

    (void)in_sizes; (void)n_in; (void)out_size;

    // 1. QKV projections (tensor-core 2-term split-TF32, presplit smem)
    dim3 gq(D_ / BN, MROWS / BM, 3);
    qkv_kernel<<<gq, 256>>>(x, Wq, Wk, Wv, bq, bk, bv);

    // 2. Windowed attention
    dim3 ga(SW / TQ, B_ * NW * H_);
    attn_kernel<<<ga, 256>>>();

    // 3. Output projection + residual -> g_q (as y)
    dim3 go(D_ / BN, MROWS / BM, 1);
    oproj_kernel<<<go, 256>>>(Wo, bo, x);

    // 4. LayerNorm -> out
    ln_kernel<<<MROWS, 256>>>(gamma, beta, out);
}